// round 2
// baseline (speedup 1.0000x reference)
#include <cuda_runtime.h>
#include <cuda_bf16.h>
#include <math.h>
#include <stdint.h>

#define B 128
#define S 512
#define T 256
#define THREADS 512
#define NSLICE 8          // i-slices (512 threads = 64 j-groups x 8 i-slices)
#define SLICE 32          // i per slice (NSLICE*SLICE = T)
#define L2E 1.4426950408889634f
#define NEG_INF (-__int_as_float(0x7f800000))

// ---------------- device scratch (static, no allocation) ----------------
__device__ __align__(16) unsigned char g_hist[(size_t)S * B * T]; // [(t*B + b)*T + j]
__device__ float g_den[B];
__device__ float g_num[B];

// ---------------- shared memory layout (bytes) ----------------
// E (ushort bf16)      [T*T]        0      .. 131072
// pv (float2: P, vs)   [T]          131072 .. 133120
// dsbuf (float)        [T]          133120 .. 134144
// accpart (float)      [NSLICE*T]   134144 .. 142336
// bestpart (float)     [NSLICE*T]   142336 .. 150528
// idxpart (int)        [NSLICE*T]   150528 .. 158720
// redf (float)         [16]         158720 .. 158784
// redi (int)           [16]         158784 .. 158848
// bcast (float)        [4]          158848 .. 158864
// ibc (int)            [4]          158864 .. 158880
#define SMEM_BYTES 159232

__device__ __forceinline__ unsigned short bf16_rn(float f) {
    unsigned int u = __float_as_uint(f);
    unsigned int r = (u + 0x7fffu + ((u >> 16) & 1u)) >> 16;
    return (unsigned short)r;
}

__device__ __forceinline__ float block_max512(float v, float* redf, float* bcast, int tid) {
    #pragma unroll
    for (int o = 16; o; o >>= 1) v = fmaxf(v, __shfl_xor_sync(0xffffffffu, v, o));
    if ((tid & 31) == 0) redf[tid >> 5] = v;
    __syncthreads();
    if (tid == 0) {
        float m = redf[0];
        #pragma unroll
        for (int w = 1; w < 16; ++w) m = fmaxf(m, redf[w]);
        bcast[0] = m;
    }
    __syncthreads();
    return bcast[0];
}

__device__ __forceinline__ float block_sum512(float v, float* redf, float* bcast, int tid) {
    #pragma unroll
    for (int o = 16; o; o >>= 1) v += __shfl_xor_sync(0xffffffffu, v, o);
    if ((tid & 31) == 0) redf[tid >> 5] = v;
    __syncthreads();
    if (tid == 0) {
        float s = 0.f;
        #pragma unroll
        for (int w = 0; w < 16; ++w) s += redf[w];
        bcast[1] = s;
    }
    __syncthreads();
    return bcast[1];
}

// argmax: max value, lowest index on ties (matches jnp.argmax)
__device__ __forceinline__ int block_argmax512(float v, int idx, float* redf, int* redi,
                                               int* ibc, int tid) {
    #pragma unroll
    for (int o = 16; o; o >>= 1) {
        float ov = __shfl_xor_sync(0xffffffffu, v, o);
        int   oi = __shfl_xor_sync(0xffffffffu, idx, o);
        if (ov > v || (ov == v && oi < idx)) { v = ov; idx = oi; }
    }
    if ((tid & 31) == 0) { redf[tid >> 5] = v; redi[tid >> 5] = idx; }
    __syncthreads();
    if (tid == 0) {
        float bv = redf[0]; int bi = redi[0];
        #pragma unroll
        for (int w = 1; w < 16; ++w) {
            float ov = redf[w]; int oi = redi[w];
            if (ov > bv || (ov == bv && oi < bi)) { bv = ov; bi = oi; }
        }
        ibc[0] = bi;
    }
    __syncthreads();
    return ibc[0];
}

__global__ void __launch_bounds__(THREADS, 1)
crf_main(const float* __restrict__ logits, const int* __restrict__ mask,
         const float* __restrict__ start_t, const float* __restrict__ end_t,
         const float* __restrict__ trans, float* __restrict__ out) {
    extern __shared__ char sm[];
    unsigned short* Esm   = (unsigned short*)(sm);
    float2*         pvbuf = (float2*)(sm + 131072);
    float*          dsbuf = (float*)(sm + 133120);
    float*          accp  = (float*)(sm + 134144);
    float*          bstp  = (float*)(sm + 142336);
    int*            idxp  = (int*)(sm + 150528);
    float*          redf  = (float*)(sm + 158720);
    int*            redi  = (int*)(sm + 158784);
    float*          bcast = (float*)(sm + 158848);
    int*            ibc   = (int*)(sm + 158864);

    const int b   = blockIdx.x;
    const int tid = threadIdx.x;
    const float* gl = logits + (size_t)b * S * T;
    const int* mrow = mask + (size_t)b * S;

    // ---- sequence length (mask is a prefix mask; marshaled as int32) ----
    {
        int cnt = 0;
        for (int s = tid; s < S; s += THREADS) cnt += (mrow[s] != 0);
        #pragma unroll
        for (int o = 16; o; o >>= 1) cnt += __shfl_xor_sync(0xffffffffu, cnt, o);
        if ((tid & 31) == 0) redi[tid >> 5] = cnt;
        __syncthreads();
        if (tid == 0) {
            int s = 0;
            #pragma unroll
            for (int w = 0; w < 16; ++w) s += redi[w];
            ibc[1] = s;
        }
    }
    // ---- fill E = exp(trans) as bf16 into SMEM ----
    for (int k = tid; k < T * T; k += THREADS) Esm[k] = bf16_rn(expf(trans[k]));
    __syncthreads();
    const int L = ibc[1];

    // ---- t = 0 init ----
    {
        float ds = NEG_INF;
        if (tid < T) ds = start_t[tid] + gl[tid];
        float m0val = block_max512(ds, redf, bcast, tid);
        if (tid < T) {
            dsbuf[tid] = ds;
            float P = exp2f((ds - m0val) * L2E);
            pvbuf[tid] = make_float2(P, ds);
        }
        __syncthreads();
    }

    const int jg4 = (tid & 63) * 4;
    const int is  = tid >> 6;
    const int i0  = is * SLICE;

    // ---- time recurrence ----
    for (int t = 1; t < L; ++t) {
        // prefetch emit early (hidden behind inner loop)
        float emit = 0.f;
        if (tid < T) emit = gl[(size_t)t * T + tid];

        float a0 = 0.f, a1 = 0.f, a2 = 0.f, a3 = 0.f;
        float v0 = NEG_INF, v1 = NEG_INF, v2 = NEG_INF, v3 = NEG_INF;
        int   x0 = 0, x1 = 0, x2 = 0, x3 = 0;

        const float*          trow = trans + (size_t)i0 * T + jg4;
        const unsigned short* erow = Esm + i0 * T + jg4;

        #pragma unroll 8
        for (int ii = 0; ii < SLICE; ++ii) {
            const int i = i0 + ii;
            float2 p = pvbuf[i];
            float4 tr = *(const float4*)(trow + (size_t)ii * T);
            uint2  eu = *(const uint2*)(erow + (size_t)ii * T);
            float e0 = __uint_as_float(eu.x << 16);
            float e1 = __uint_as_float(eu.x & 0xffff0000u);
            float e2 = __uint_as_float(eu.y << 16);
            float e3 = __uint_as_float(eu.y & 0xffff0000u);
            a0 = fmaf(p.x, e0, a0);
            a1 = fmaf(p.x, e1, a1);
            a2 = fmaf(p.x, e2, a2);
            a3 = fmaf(p.x, e3, a3);
            float c0 = p.y + tr.x;  if (c0 > v0) { v0 = c0; x0 = i; }
            float c1 = p.y + tr.y;  if (c1 > v1) { v1 = c1; x1 = i; }
            float c2 = p.y + tr.z;  if (c2 > v2) { v2 = c2; x2 = i; }
            float c3 = p.y + tr.w;  if (c3 > v3) { v3 = c3; x3 = i; }
        }
        {
            const int base = is * T + jg4;
            accp[base + 0] = a0; accp[base + 1] = a1; accp[base + 2] = a2; accp[base + 3] = a3;
            bstp[base + 0] = v0; bstp[base + 1] = v1; bstp[base + 2] = v2; bstp[base + 3] = v3;
            idxp[base + 0] = x0; idxp[base + 1] = x1; idxp[base + 2] = x2; idxp[base + 3] = x3;
        }
        __syncthreads();

        const float m = bcast[0];   // max of ds from step t-1
        if (tid < T) {
            const int j = tid;
            float asum = 0.f;
            float bv = NEG_INF;
            int   bi = 0;
            #pragma unroll
            for (int sI = 0; sI < NSLICE; ++sI) {
                asum += accp[sI * T + j];
                float v = bstp[sI * T + j];
                if (v > bv) { bv = v; bi = idxp[sI * T + j]; }   // ascending slices -> first-idx tie
            }
            float dsn = m + logf(asum) + emit;
            float vsn = bv + emit;
            g_hist[((size_t)t * B + b) * T + j] = (unsigned char)bi;
            dsbuf[j] = dsn;
            float mn = block_max512(dsn, redf, bcast, tid);
            float P = exp2f((dsn - mn) * L2E);
            pvbuf[j] = make_float2(P, vsn);
        } else {
            (void)block_max512(NEG_INF, redf, bcast, tid);
        }
        __syncthreads();
    }

    // ---- finish denominator: logsumexp(ds + end) ----
    {
        float xd = NEG_INF;
        if (tid < T) xd = dsbuf[tid] + end_t[tid];
        float m2 = block_max512(xd, redf, bcast, tid);
        float c = (tid < T) ? exp2f((xd - m2) * L2E) : 0.f;
        float ssum = block_sum512(c, redf, bcast, tid);
        if (tid == 0) g_den[b] = m2 + logf(ssum);
    }
    // ---- viterbi last tag: argmax(vs + end) ----
    int last;
    {
        float xv = NEG_INF;
        int idx = 0x7fffffff;
        if (tid < T) { xv = pvbuf[tid].y + end_t[tid]; idx = tid; }
        last = block_argmax512(xv, idx, redf, redi, ibc, tid);
    }
    __syncthreads();

    // ---- backtrack: copy this batch's history into SMEM (reusing E region) ----
    unsigned char* hsm = (unsigned char*)Esm;   // L*T <= 512*256 = 131072 bytes fits exactly
    for (int f = tid; f < L * (T / 16); f += THREADS) {
        int row = f >> 4;
        int off = f & 15;
        ((uint4*)hsm)[f] = ((const uint4*)(g_hist + ((size_t)row * B + b) * T))[off];
    }
    __syncthreads();

    float* outp = out + (size_t)b * S;
    for (int s = L + tid; s < S; s += THREADS) outp[s] = 0.0f;  // masked -> 0
    if (tid == 0) {
        int tag = last;
        outp[L - 1] = (float)tag;
        for (int t = L - 2; t >= 0; --t) {
            tag = hsm[(t + 1) * T + tag];
            outp[t] = (float)tag;
        }
    }
}

// ---------------- numerator ----------------
__global__ void __launch_bounds__(256)
crf_num(const float* __restrict__ logits, const int* __restrict__ mask,
        const int* __restrict__ labels, const float* __restrict__ start_t,
        const float* __restrict__ end_t, const float* __restrict__ trans) {
    __shared__ float redf[8];
    __shared__ int   redi[8];
    const int b = blockIdx.x;
    const int tid = threadIdx.x;
    const int* lab = labels + (size_t)b * S;
    const float* gl = logits + (size_t)b * S * T;
    const int* mrow = mask + (size_t)b * S;

    float part = 0.f;
    int cnt = 0;
    for (int s = tid; s < S; s += 256) cnt += (mrow[s] != 0);
    for (int s = 1 + tid; s < S; s += 256) {
        if (mrow[s]) {
            int ls = lab[s];
            int lp = lab[s - 1];
            part += trans[lp * T + ls] + gl[(size_t)s * T + ls];
        }
    }
    #pragma unroll
    for (int o = 16; o; o >>= 1) {
        part += __shfl_xor_sync(0xffffffffu, part, o);
        cnt  += __shfl_xor_sync(0xffffffffu, cnt, o);
    }
    if ((tid & 31) == 0) { redf[tid >> 5] = part; redi[tid >> 5] = cnt; }
    __syncthreads();
    if (tid == 0) {
        float s = 0.f; int L = 0;
        #pragma unroll
        for (int w = 0; w < 8; ++w) { s += redf[w]; L += redi[w]; }
        int l0 = lab[0];
        int ll = lab[L - 1];
        g_num[b] = s + start_t[l0] + gl[l0] + end_t[ll];
    }
}

// ---------------- loss ----------------
__global__ void __launch_bounds__(128)
crf_loss(float* __restrict__ out) {
    __shared__ float redf[4];
    const int tid = threadIdx.x;
    float d = g_num[tid] - g_den[tid];
    #pragma unroll
    for (int o = 16; o; o >>= 1) d += __shfl_xor_sync(0xffffffffu, d, o);
    if ((tid & 31) == 0) redf[tid >> 5] = d;
    __syncthreads();
    if (tid == 0) {
        float s = redf[0] + redf[1] + redf[2] + redf[3];
        out[(size_t)B * S] = -(s / (float)B);
    }
}

// ---------------- launch ----------------
extern "C" void kernel_launch(void* const* d_in, const int* in_sizes, int n_in,
                              void* d_out, int out_size) {
    const float* logits = (const float*)d_in[0];
    const int*   mask   = (const int*)d_in[1];
    const int*   labels = (const int*)d_in[2];
    const float* start  = (const float*)d_in[3];
    const float* endt   = (const float*)d_in[4];
    const float* trans  = (const float*)d_in[5];
    float*       out    = (float*)d_out;

    cudaFuncSetAttribute(crf_main, cudaFuncAttributeMaxDynamicSharedMemorySize, SMEM_BYTES);

    crf_main<<<B, THREADS, SMEM_BYTES>>>(logits, mask, start, endt, trans, out);
    crf_num<<<B, 256>>>(logits, mask, labels, start, endt, trans);
    crf_loss<<<1, 128>>>(out);
}

// round 3
// speedup vs baseline: 2.3984x; 2.3984x over previous
#include <cuda_runtime.h>
#include <cuda_bf16.h>
#include <math.h>
#include <stdint.h>

#define B 128
#define S 512
#define T 256
#define THREADS 640          // 512 LSE threads + 128 Viterbi threads
#define L2E 1.4426950408889634f
#define NEG_INF (-__int_as_float(0x7f800000))

#define BAR_LSE() asm volatile("bar.sync 1, 512;" ::: "memory")
#define BAR_VIT() asm volatile("bar.sync 2, 128;" ::: "memory")

// ---------------- device scratch (static, no allocation) ----------------
__device__ __align__(16) unsigned char g_hist[(size_t)S * B * T]; // [(t*B + b)*T + j]
__device__ float g_den[B];
__device__ float g_num[B];

// ---------------- shared memory layout (bytes) ----------------
#define OFF_E      0         // ushort bf16 E[T*T]           131072
#define OFF_P      131072    // float P[T]                   1024
#define OFF_DS     132096    // float ds[T]                  1024
#define OFF_ACC    133120    // float accp[8*T]              8192
#define OFF_REDF   141312    // float redf[32]               128
#define OFF_REDI   141440    // int   redi[32]               128
#define OFF_BCAST  141568    // float bcast[4]               16
#define OFF_IBC    141584    // int   ibc[4]                 16
#define OFF_VS     141600    // float vs[T]                  1024
#define OFF_RMAX   142624    // float rowmax[T]              1024
#define OFF_RMIN   143648    // float rowmin[T]              1024
#define OFF_CI     144672    // int   cand_i[T]              1024
#define OFF_CV     145696    // float cand_v[T]              1024
#define OFF_VRED   146720    // float vred[8]                32
#define OFF_WCNT   146752    // int   wcnt[8]                32
#define OFF_VIBC   146784    // int   vibc[4]                16
#define SMEM_BYTES 146944

__device__ __forceinline__ unsigned short bf16_rn(float f) {
    unsigned int u = __float_as_uint(f);
    unsigned int r = (u + 0x7fffu + ((u >> 16) & 1u)) >> 16;
    return (unsigned short)r;
}

__global__ void __launch_bounds__(THREADS, 1)
crf_main(const float* __restrict__ logits, const int* __restrict__ mask,
         const float* __restrict__ start_t, const float* __restrict__ end_t,
         const float* __restrict__ trans, float* __restrict__ out) {
    extern __shared__ char sm[];
    unsigned short* Esm   = (unsigned short*)(sm + OFF_E);
    float*          Psm   = (float*)(sm + OFF_P);
    float*          dsbuf = (float*)(sm + OFF_DS);
    float*          accp  = (float*)(sm + OFF_ACC);
    float*          redf  = (float*)(sm + OFF_REDF);
    int*            redi  = (int*)(sm + OFF_REDI);
    int*            ibc   = (int*)(sm + OFF_IBC);
    float*          vssm  = (float*)(sm + OFF_VS);
    float*          rmax  = (float*)(sm + OFF_RMAX);
    float*          rmin  = (float*)(sm + OFF_RMIN);
    int*            cidx  = (int*)(sm + OFF_CI);
    float*          cval  = (float*)(sm + OFF_CV);
    float*          vred  = (float*)(sm + OFF_VRED);
    int*            wcnt  = (int*)(sm + OFF_WCNT);
    int*            vibc  = (int*)(sm + OFF_VIBC);

    const int b   = blockIdx.x;
    const int tid = threadIdx.x;
    const int wid = tid >> 5;
    const int lane = tid & 31;
    const float* gl = logits + (size_t)b * S * T;
    const int* mrow = mask + (size_t)b * S;

    // ================= init (full block) =================
    // sequence length (prefix mask, int32)
    {
        int cnt = 0;
        for (int s = tid; s < S; s += THREADS) cnt += (mrow[s] != 0);
        #pragma unroll
        for (int o = 16; o; o >>= 1) cnt += __shfl_xor_sync(0xffffffffu, cnt, o);
        if (lane == 0) redi[wid] = cnt;
    }
    // E = exp(trans) bf16
    for (int k = tid; k < T * T; k += THREADS) Esm[k] = bf16_rn(expf(trans[k]));
    // row max / min of trans (threads 0..255, one row each)
    if (tid < T) {
        float mx = NEG_INF, mn = -NEG_INF;
        const float4* tr4 = (const float4*)(trans + (size_t)tid * T);
        #pragma unroll 8
        for (int c = 0; c < T / 4; ++c) {
            float4 v = tr4[c];
            mx = fmaxf(fmaxf(mx, v.x), fmaxf(v.y, fmaxf(v.z, v.w)));
            mn = fminf(fminf(mn, v.x), fminf(v.y, fminf(v.z, v.w)));
        }
        rmax[tid] = mx;
        rmin[tid] = mn;
    }
    __syncthreads();
    if (tid == 0) {
        int s = 0;
        #pragma unroll
        for (int w = 0; w < THREADS / 32; ++w) s += redi[w];
        ibc[0] = s;
    }
    // t = 0 init: ds0 = vs0 = start + logits[0]
    float ds0 = NEG_INF;
    if (tid < T) {
        ds0 = start_t[tid] + gl[tid];
        dsbuf[tid] = ds0;
        vssm[tid]  = ds0;
    }
    {
        float v = ds0;
        #pragma unroll
        for (int o = 16; o; o >>= 1) v = fmaxf(v, __shfl_xor_sync(0xffffffffu, v, o));
        if (lane == 0) redf[wid] = v;
    }
    __syncthreads();
    float m0 = redf[0];
    #pragma unroll
    for (int w = 1; w < THREADS / 32; ++w) m0 = fmaxf(m0, redf[w]);
    if (tid < T) Psm[tid] = exp2f((ds0 - m0) * L2E);
    const int L = ibc[0];
    __syncthreads();

    // ================= specialized main loops =================
    if (tid < 512) {
        // ---------------- LSE group (16 warps) ----------------
        const int jg4 = (tid & 63) * 4;
        const int i0  = (tid >> 6) * 32;
        const int is  = tid >> 6;
        float m_prev = m0;
        const unsigned short* erow = Esm + i0 * T + jg4;

        for (int t = 1; t < L; ++t) {
            float emit = 0.f;
            if (tid < T) emit = gl[(size_t)t * T + tid];

            float a0 = 0.f, a1 = 0.f, a2 = 0.f, a3 = 0.f;
            #pragma unroll
            for (int ii = 0; ii < 32; ii += 4) {
                float4 p4 = *(const float4*)(Psm + i0 + ii);
                {
                    uint2 eu = *(const uint2*)(erow + (ii + 0) * T);
                    a0 = fmaf(p4.x, __uint_as_float(eu.x << 16), a0);
                    a1 = fmaf(p4.x, __uint_as_float(eu.x & 0xffff0000u), a1);
                    a2 = fmaf(p4.x, __uint_as_float(eu.y << 16), a2);
                    a3 = fmaf(p4.x, __uint_as_float(eu.y & 0xffff0000u), a3);
                }
                {
                    uint2 eu = *(const uint2*)(erow + (ii + 1) * T);
                    a0 = fmaf(p4.y, __uint_as_float(eu.x << 16), a0);
                    a1 = fmaf(p4.y, __uint_as_float(eu.x & 0xffff0000u), a1);
                    a2 = fmaf(p4.y, __uint_as_float(eu.y << 16), a2);
                    a3 = fmaf(p4.y, __uint_as_float(eu.y & 0xffff0000u), a3);
                }
                {
                    uint2 eu = *(const uint2*)(erow + (ii + 2) * T);
                    a0 = fmaf(p4.z, __uint_as_float(eu.x << 16), a0);
                    a1 = fmaf(p4.z, __uint_as_float(eu.x & 0xffff0000u), a1);
                    a2 = fmaf(p4.z, __uint_as_float(eu.y << 16), a2);
                    a3 = fmaf(p4.z, __uint_as_float(eu.y & 0xffff0000u), a3);
                }
                {
                    uint2 eu = *(const uint2*)(erow + (ii + 3) * T);
                    a0 = fmaf(p4.w, __uint_as_float(eu.x << 16), a0);
                    a1 = fmaf(p4.w, __uint_as_float(eu.x & 0xffff0000u), a1);
                    a2 = fmaf(p4.w, __uint_as_float(eu.y << 16), a2);
                    a3 = fmaf(p4.w, __uint_as_float(eu.y & 0xffff0000u), a3);
                }
            }
            *(float4*)(accp + is * T + jg4) = make_float4(a0, a1, a2, a3);
            BAR_LSE();

            float dsn = 0.f, wmax = NEG_INF;
            if (tid < T) {
                float asum = 0.f;
                #pragma unroll
                for (int s2 = 0; s2 < 8; ++s2) asum += accp[s2 * T + tid];
                dsn = m_prev + logf(asum) + emit;
                dsbuf[tid] = dsn;
                wmax = dsn;
            }
            #pragma unroll
            for (int o = 16; o; o >>= 1) wmax = fmaxf(wmax, __shfl_xor_sync(0xffffffffu, wmax, o));
            if (tid < T && lane == 0) redf[wid] = wmax;
            BAR_LSE();
            if (tid < T) {
                float mn = redf[0];
                #pragma unroll
                for (int w = 1; w < 8; ++w) mn = fmaxf(mn, redf[w]);
                Psm[tid] = exp2f((dsn - mn) * L2E);
                m_prev = mn;
            }
            BAR_LSE();
        }
    } else {
        // ---------------- Viterbi group (4 warps, pruned) ----------------
        const int vtid = tid - 512;         // 0..127
        const int vwid = vtid >> 5;         // 0..3
        const int vlane = vtid & 31;
        const int j0 = 2 * vtid;            // this thread owns columns j0, j0+1
        const int i0c = 2 * vtid;           // and screens rows i0c, i0c+1

        for (int t = 1; t < L; ++t) {
            float2 em = *(const float2*)(gl + (size_t)t * T + j0);   // prefetch emit
            float2 v2  = *(const float2*)(vssm + i0c);
            float2 rn2 = *(const float2*)(rmin + i0c);
            float2 rx2 = *(const float2*)(rmax + i0c);

            // threshold = max_i (vs_i + rowmin_i)
            float sthr = fmaxf(v2.x + rn2.x, v2.y + rn2.y);
            #pragma unroll
            for (int o = 16; o; o >>= 1) sthr = fmaxf(sthr, __shfl_xor_sync(0xffffffffu, sthr, o));
            if (vlane == 0) vred[vwid] = sthr;
            BAR_VIT();
            float thresh = fmaxf(fmaxf(vred[0], vred[1]), fmaxf(vred[2], vred[3]));

            // candidate compaction (ascending i; winner set is certified)
            int q0 = (v2.x + rx2.x >= thresh) ? 1 : 0;
            int q1 = (v2.y + rx2.y >= thresh) ? 1 : 0;
            int cnt = q0 + q1;
            int incl = cnt;
            #pragma unroll
            for (int o = 1; o < 32; o <<= 1) {
                int n = __shfl_up_sync(0xffffffffu, incl, o);
                if (vlane >= o) incl += n;
            }
            int excl = incl - cnt;
            if (vlane == 31) wcnt[vwid] = incl;
            BAR_VIT();
            int base = 0;
            #pragma unroll
            for (int w = 0; w < 4; ++w) base += (w < vwid) ? wcnt[w] : 0;
            int nc = wcnt[0] + wcnt[1] + wcnt[2] + wcnt[3];
            int pos = base + excl;
            if (q0) { cidx[pos] = i0c;     cval[pos] = v2.x; pos++; }
            if (q1) { cidx[pos] = i0c + 1; cval[pos] = v2.y; }
            BAR_VIT();

            // gather over candidates (first-index tie-break: ascending + strict >)
            float b1 = NEG_INF, b2 = NEG_INF;
            int x1 = 0, x2 = 0;
            int c = 0;
            for (; c + 4 <= nc; c += 4) {
                int   ia = cidx[c], ibx = cidx[c+1], ic = cidx[c+2], id = cidx[c+3];
                float va = cval[c], vb = cval[c+1], vc = cval[c+2], vd = cval[c+3];
                float2 ta = *(const float2*)(trans + (size_t)ia  * T + j0);
                float2 tb = *(const float2*)(trans + (size_t)ibx * T + j0);
                float2 tc = *(const float2*)(trans + (size_t)ic  * T + j0);
                float2 td = *(const float2*)(trans + (size_t)id  * T + j0);
                float c1, c2;
                c1 = va + ta.x; if (c1 > b1) { b1 = c1; x1 = ia; }
                c2 = va + ta.y; if (c2 > b2) { b2 = c2; x2 = ia; }
                c1 = vb + tb.x; if (c1 > b1) { b1 = c1; x1 = ibx; }
                c2 = vb + tb.y; if (c2 > b2) { b2 = c2; x2 = ibx; }
                c1 = vc + tc.x; if (c1 > b1) { b1 = c1; x1 = ic; }
                c2 = vc + tc.y; if (c2 > b2) { b2 = c2; x2 = ic; }
                c1 = vd + td.x; if (c1 > b1) { b1 = c1; x1 = id; }
                c2 = vd + td.y; if (c2 > b2) { b2 = c2; x2 = id; }
            }
            for (; c < nc; ++c) {
                int   ia = cidx[c];
                float va = cval[c];
                float2 ta = *(const float2*)(trans + (size_t)ia * T + j0);
                float c1 = va + ta.x; if (c1 > b1) { b1 = c1; x1 = ia; }
                float c2 = va + ta.y; if (c2 > b2) { b2 = c2; x2 = ia; }
            }

            // update vs, write history (safe: all reads of old vs done before last BAR)
            *(float2*)(vssm + j0) = make_float2(b1 + em.x, b2 + em.y);
            *(unsigned short*)(g_hist + ((size_t)t * B + b) * T + j0) =
                (unsigned short)((unsigned)x1 | ((unsigned)x2 << 8));
            BAR_VIT();
        }
    }
    __syncthreads();   // join groups

    // ================= epilogue (full block) =================
    // denominator: logsumexp(ds + end)
    {
        float xd = NEG_INF;
        if (tid < T) xd = dsbuf[tid] + end_t[tid];
        float v = xd;
        #pragma unroll
        for (int o = 16; o; o >>= 1) v = fmaxf(v, __shfl_xor_sync(0xffffffffu, v, o));
        if (lane == 0) redf[wid] = v;
        __syncthreads();
        float m2 = redf[0];
        #pragma unroll
        for (int w = 1; w < THREADS / 32; ++w) m2 = fmaxf(m2, redf[w]);
        float cs = (tid < T) ? exp2f((xd - m2) * L2E) : 0.f;
        #pragma unroll
        for (int o = 16; o; o >>= 1) cs += __shfl_xor_sync(0xffffffffu, cs, o);
        __syncthreads();           // protect redf reuse
        if (lane == 0) redf[wid] = cs;
        __syncthreads();
        if (tid == 0) {
            float ssum = 0.f;
            #pragma unroll
            for (int w = 0; w < THREADS / 32; ++w) ssum += redf[w];
            g_den[b] = m2 + logf(ssum);
        }
    }
    // viterbi last tag: argmax(vs + end), lowest index on ties
    {
        float xv = NEG_INF;
        int idx = 0x7fffffff;
        if (tid < T) { xv = vssm[tid] + end_t[tid]; idx = tid; }
        #pragma unroll
        for (int o = 16; o; o >>= 1) {
            float ov = __shfl_xor_sync(0xffffffffu, xv, o);
            int   oi = __shfl_xor_sync(0xffffffffu, idx, o);
            if (ov > xv || (ov == xv && oi < idx)) { xv = ov; idx = oi; }
        }
        __syncthreads();           // protect redf/redi reuse
        if (lane == 0) { redf[wid] = xv; redi[wid] = idx; }
        __syncthreads();
        if (tid == 0) {
            float bv = redf[0]; int bi = redi[0];
            #pragma unroll
            for (int w = 1; w < THREADS / 32; ++w) {
                float ov = redf[w]; int oi = redi[w];
                if (ov > bv || (ov == bv && oi < bi)) { bv = ov; bi = oi; }
            }
            vibc[0] = bi;
        }
        __syncthreads();
    }
    const int last = vibc[0];

    // backtrack: copy this batch's history into SMEM (reusing E region)
    unsigned char* hsm = (unsigned char*)Esm;   // L*T <= 131072 bytes
    for (int f = tid; f < L * (T / 16); f += THREADS) {
        int row = f >> 4;
        int off = f & 15;
        ((uint4*)hsm)[f] = ((const uint4*)(g_hist + ((size_t)row * B + b) * T))[off];
    }
    __syncthreads();

    float* outp = out + (size_t)b * S;
    for (int s = L + tid; s < S; s += THREADS) outp[s] = 0.0f;  // masked -> 0
    if (tid == 0) {
        int tag = last;
        outp[L - 1] = (float)tag;
        for (int t = L - 2; t >= 0; --t) {
            tag = hsm[(t + 1) * T + tag];
            outp[t] = (float)tag;
        }
    }
}

// ---------------- numerator ----------------
__global__ void __launch_bounds__(256)
crf_num(const float* __restrict__ logits, const int* __restrict__ mask,
        const int* __restrict__ labels, const float* __restrict__ start_t,
        const float* __restrict__ end_t, const float* __restrict__ trans) {
    __shared__ float redf[8];
    __shared__ int   redi[8];
    const int b = blockIdx.x;
    const int tid = threadIdx.x;
    const int* lab = labels + (size_t)b * S;
    const float* gl = logits + (size_t)b * S * T;
    const int* mrow = mask + (size_t)b * S;

    float part = 0.f;
    int cnt = 0;
    for (int s = tid; s < S; s += 256) cnt += (mrow[s] != 0);
    for (int s = 1 + tid; s < S; s += 256) {
        if (mrow[s]) {
            int ls = lab[s];
            int lp = lab[s - 1];
            part += trans[lp * T + ls] + gl[(size_t)s * T + ls];
        }
    }
    #pragma unroll
    for (int o = 16; o; o >>= 1) {
        part += __shfl_xor_sync(0xffffffffu, part, o);
        cnt  += __shfl_xor_sync(0xffffffffu, cnt, o);
    }
    if ((tid & 31) == 0) { redf[tid >> 5] = part; redi[tid >> 5] = cnt; }
    __syncthreads();
    if (tid == 0) {
        float s = 0.f; int L = 0;
        #pragma unroll
        for (int w = 0; w < 8; ++w) { s += redf[w]; L += redi[w]; }
        int l0 = lab[0];
        int ll = lab[L - 1];
        g_num[b] = s + start_t[l0] + gl[l0] + end_t[ll];
    }
}

// ---------------- loss ----------------
__global__ void __launch_bounds__(128)
crf_loss(float* __restrict__ out) {
    __shared__ float redf[4];
    const int tid = threadIdx.x;
    float d = g_num[tid] - g_den[tid];
    #pragma unroll
    for (int o = 16; o; o >>= 1) d += __shfl_xor_sync(0xffffffffu, d, o);
    if ((tid & 31) == 0) redf[tid >> 5] = d;
    __syncthreads();
    if (tid == 0) {
        float s = redf[0] + redf[1] + redf[2] + redf[3];
        out[(size_t)B * S] = -(s / (float)B);
    }
}

// ---------------- launch ----------------
extern "C" void kernel_launch(void* const* d_in, const int* in_sizes, int n_in,
                              void* d_out, int out_size) {
    const float* logits = (const float*)d_in[0];
    const int*   mask   = (const int*)d_in[1];
    const int*   labels = (const int*)d_in[2];
    const float* start  = (const float*)d_in[3];
    const float* endt   = (const float*)d_in[4];
    const float* trans  = (const float*)d_in[5];
    float*       out    = (float*)d_out;

    cudaFuncSetAttribute(crf_main, cudaFuncAttributeMaxDynamicSharedMemorySize, SMEM_BYTES);

    crf_main<<<B, THREADS, SMEM_BYTES>>>(logits, mask, start, endt, trans, out);
    crf_num<<<B, 256>>>(logits, mask, labels, start, endt, trans);
    crf_loss<<<1, 128>>>(out);
}